// round 11
// baseline (speedup 1.0000x reference)
#include <cuda_runtime.h>
#include <cuda_fp16.h>
#include <cstdint>

// ===========================================================================
// SparseResBlock3D — dense mma.sync fp16 (fp32 accumulate).
// CTA = 256 rows x 128 cols, 8 warps, warp tile m64 x n64 (4 B/output-el of
// LDSM traffic vs 6 B/el previously -> tensor pipe becomes dominant).
//   film = silu(emb) @ emb_W + emb_b
//   h1   = fp16(silu(LN(feats; g,b)))                      -> g_bufA
//   h3   = fp16(silu(LN(conv27(h1,W1)+b1)*(1+s[b])+sh[b])) -> g_bufH3 (fused)
//   out  = conv27(h3, W2) + b2 + feats
// ===========================================================================

#define NROWS     200000
#define C         128
#define TAPS      27
#define ROWS_CTA  256          // CTA output tile rows
#define NC        54           // K-chunks: 27 taps * 2 (K=64 each)
#define NSTAGE    3
#define STAGE_BYTES 49152      // A(32K fp16 256x64) + B(16K fp16 128x64)
#define STAGES_OFF  28672      // idx region: 256*27*4 = 27648B, padded
#define DYN_SMEM  (STAGES_OFF + NSTAGE * STAGE_BYTES)   // 176128 B
#define ACC_PITCH 132          // fp32 epilogue tile pitch (floats)

// ---- scratch (static device globals) ----
__device__ __half g_bufA[(size_t)NROWS * C];    // fp16 h1 (conv1 input)
__device__ __half g_bufH3[(size_t)NROWS * C];   // fp16 h3 (conv2 input)
__device__ float  g_film[4 * 256];              // [b][0:128]=1+scale, [128:256]=shift
__device__ __half g_WT1[(size_t)NC * 8192];     // pre-swizzled fp16 W^T chunks
__device__ __half g_WT2[(size_t)NC * 8192];

// ---------------------------------------------------------------------------
// helpers
// ---------------------------------------------------------------------------
__device__ __forceinline__ float silu_f(float x) { return x / (1.0f + expf(-x)); }

__device__ __forceinline__ uint32_t smem_u32(const void* p) {
    uint32_t a;
    asm("{ .reg .u64 t; cvta.to.shared.u64 t, %1; cvt.u32.u64 %0, t; }" : "=r"(a) : "l"(p));
    return a;
}

__device__ __forceinline__ void cp_async16(uint32_t dst, const void* src, int src_bytes) {
    asm volatile("cp.async.cg.shared.global [%0], [%1], 16, %2;"
                 :: "r"(dst), "l"(src), "r"(src_bytes));
}
__device__ __forceinline__ void cp_commit() {
    asm volatile("cp.async.commit_group;");
}
template <int N> __device__ __forceinline__ void cp_wait() {
    asm volatile("cp.async.wait_group %0;" :: "n"(N));
}

__device__ __forceinline__ void ldsm4(uint32_t* r, uint32_t addr) {
    asm volatile("ldmatrix.sync.aligned.m8n8.x4.shared.b16 {%0,%1,%2,%3}, [%4];"
                 : "=r"(r[0]), "=r"(r[1]), "=r"(r[2]), "=r"(r[3]) : "r"(addr));
}

__device__ __forceinline__ void mma_f16(float* d, const uint32_t* a,
                                        uint32_t b0, uint32_t b1) {
    asm volatile(
        "mma.sync.aligned.m16n8k16.row.col.f32.f16.f16.f32 "
        "{%0,%1,%2,%3}, {%4,%5,%6,%7}, {%8,%9}, {%0,%1,%2,%3};"
        : "+f"(d[0]), "+f"(d[1]), "+f"(d[2]), "+f"(d[3])
        : "r"(a[0]), "r"(a[1]), "r"(a[2]), "r"(a[3]), "r"(b0), "r"(b1));
}

// ---------------------------------------------------------------------------
// FiLM embedding GEMM.  grid=(4), block=256.
// ---------------------------------------------------------------------------
__global__ void film_kernel(const float* __restrict__ emb,
                            const float* __restrict__ embW,
                            const float* __restrict__ embb) {
    __shared__ float s[512];
    int b = blockIdx.x;
    int c = threadIdx.x;
    for (int e = c; e < 512; e += 256) s[e] = silu_f(emb[b * 512 + e]);
    __syncthreads();
    float acc = embb[c];
#pragma unroll 8
    for (int e = 0; e < 512; ++e) acc = fmaf(s[e], embW[e * 256 + c], acc);
    g_film[b * 256 + c] = (c < 128) ? (1.0f + acc) : acc;
}

// ---------------------------------------------------------------------------
// LN(gamma,beta) + SiLU -> fp16 g_bufA.  One warp per row.
// ---------------------------------------------------------------------------
__global__ void ln_silu_kernel(const float* __restrict__ x,
                               const float* __restrict__ gamma,
                               const float* __restrict__ beta) {
    int row  = blockIdx.x * 8 + (threadIdx.x >> 5);
    int lane = threadIdx.x & 31;
    float4 v = reinterpret_cast<const float4*>(x + (size_t)row * C)[lane];
    float s  = v.x + v.y + v.z + v.w;
    float ss = v.x * v.x + v.y * v.y + v.z * v.z + v.w * v.w;
#pragma unroll
    for (int o = 16; o > 0; o >>= 1) {
        s  += __shfl_xor_sync(0xffffffffu, s, o);
        ss += __shfl_xor_sync(0xffffffffu, ss, o);
    }
    float mu  = s * (1.0f / 128.0f);
    float inv = rsqrtf(ss * (1.0f / 128.0f) - mu * mu + 1e-6f);
    float4 g  = reinterpret_cast<const float4*>(gamma)[lane];
    float4 be = reinterpret_cast<const float4*>(beta)[lane];
    __half2 h0 = __floats2half2_rn(silu_f((v.x - mu) * inv * g.x + be.x),
                                   silu_f((v.y - mu) * inv * g.y + be.y));
    __half2 h1 = __floats2half2_rn(silu_f((v.z - mu) * inv * g.z + be.z),
                                   silu_f((v.w - mu) * inv * g.w + be.w));
    __half2* dst = reinterpret_cast<__half2*>(g_bufA + (size_t)row * C);
    dst[lane * 2]     = h0;
    dst[lane * 2 + 1] = h1;
}

// ---------------------------------------------------------------------------
// Weight prep: transpose to [N,K], fp16-round, XOR-swizzle, pack per chunk.
// ---------------------------------------------------------------------------
__global__ void wprep_kernel(const float* __restrict__ W, __half* __restrict__ WT) {
    int c = blockIdx.x;
    int k = c >> 1, q = c & 1;
    for (int e = threadIdx.x; e < 8192; e += 256) {
        int nn = e >> 6, w = e & 63;
        __half v = __float2half_rn(W[((size_t)k * 128 + q * 64 + w) * 128 + nn]);
        int off = nn * 128 + w * 2;                       // byte offset in tile
        WT[(size_t)c * 8192 + ((off ^ ((off >> 3) & 0x70)) >> 1)] = v;
    }
}

// ---------------------------------------------------------------------------
// Dense mma.sync fp16 sparse conv. 256 threads (8 warps), CTA 256x128.
// Warp tile m64 x n64 (4 m-warps x 2 n-warps). 3-stage cp.async pipeline,
// one barrier per chunk.
// ---------------------------------------------------------------------------
template <bool FUSE_LN>
__global__ void __launch_bounds__(256, 1)
conv_mma_kernel(const __half* __restrict__ src,
                const int*    __restrict__ nbr,
                const __half* __restrict__ WT,
                const float*  __restrict__ bias,
                const float*  __restrict__ residual,
                float*        __restrict__ out,
                __half*       __restrict__ h3_out,
                const int*    __restrict__ batch_idx,
                int n) {
    extern __shared__ char dsm[];
    int* idxsh = reinterpret_cast<int*>(dsm);

    const int tid  = threadIdx.x;
    const int wid  = tid >> 5;
    const int lane = tid & 31;
    const int row0 = blockIdx.x * ROWS_CTA;
    const uint32_t dsm_u32 = smem_u32(dsm);

    // --- stage neighbor indices (tail rows forced invalid) ---
    for (int l = tid; l < ROWS_CTA * TAPS; l += 256) {
        int gr = row0 + l / TAPS;
        idxsh[l] = (gr < n) ? nbr[(size_t)gr * TAPS + (l % TAPS)] : -1;
    }
    __syncthreads();

    // loader: 1 thread per row (256 rows), 128B each; B: 64B per thread
    auto load_chunk = [&](int c) {
        int st = c % NSTAGE;
        uint32_t sb = dsm_u32 + STAGES_OFF + st * STAGE_BYTES;
        int k = c >> 1, q = c & 1;
        int idx = idxsh[tid * TAPS + k];
        const __half* srow = src + (size_t)(idx < 0 ? 0 : idx) * C + q * 64;
        int bytes = (idx < 0) ? 0 : 16;
#pragma unroll
        for (int i = 0; i < 8; ++i) {
            int off = tid * 128 + i * 16;
            cp_async16(sb + (off ^ ((off >> 3) & 0x70)), srow + i * 8, bytes);
        }
        const __half* bsrc = WT + (size_t)c * 8192 + tid * 32;
        uint32_t bd = sb + 32768 + tid * 64;
#pragma unroll
        for (int i = 0; i < 4; ++i) cp_async16(bd + i * 16, bsrc + i * 8, 16);
        cp_commit();
    };

    // --- warp tiling: wm=wid&3 -> rows 64*wm..+64 ; wn=wid>>2 -> cols 64*wn ---
    const int wm = wid & 3;
    const int wn = wid >> 2;

    uint32_t a_rowoff[4];
    int      a_ph[4];
#pragma unroll
    for (int mt = 0; mt < 4; ++mt) {
        int r = 64 * wm + 16 * mt + (lane & 15);
        a_rowoff[mt] = r * 128;
        a_ph[mt]     = r & 7;
    }
    const int a_kbh = lane >> 4;

    uint32_t b_rowoff[4];
    int      b_ph[4];
#pragma unroll
    for (int np = 0; np < 4; ++np) {
        int r = 64 * wn + 16 * np + (lane & 7) + ((lane >> 4) << 3);
        b_rowoff[np] = 32768 + r * 128;
        b_ph[np]     = r & 7;
    }
    const int b_kbh = (lane >> 3) & 1;

    float d[4][8][4];
#pragma unroll
    for (int mt = 0; mt < 4; ++mt)
#pragma unroll
        for (int nt = 0; nt < 8; ++nt)
#pragma unroll
            for (int j = 0; j < 4; ++j) d[mt][nt][j] = 0.0f;

    // prologue
    load_chunk(0);
    load_chunk(1);

    for (int c = 0; c < NC; ++c) {
        if (c < NC - 1) cp_wait<1>(); else cp_wait<0>();
        __syncthreads();

        if (c + 2 < NC) load_chunk(c + 2);   // issue prefetch BEFORE compute

        uint32_t sb = dsm_u32 + STAGES_OFF + (c % NSTAGE) * STAGE_BYTES;

#pragma unroll
        for (int ks = 0; ks < 4; ++ks) {              // 4 x k16 = K64
            uint32_t a[4][4];
#pragma unroll
            for (int mt = 0; mt < 4; ++mt)
                ldsm4(a[mt], sb + a_rowoff[mt] + ((((ks << 1) | a_kbh) ^ a_ph[mt]) << 4));
#pragma unroll
            for (int np = 0; np < 4; ++np) {
                uint32_t b[4];
                ldsm4(b, sb + b_rowoff[np] + ((((ks << 1) | b_kbh) ^ b_ph[np]) << 4));
#pragma unroll
                for (int mt = 0; mt < 4; ++mt) {
                    mma_f16(d[mt][2 * np],     a[mt], b[0], b[1]);
                    mma_f16(d[mt][2 * np + 1], a[mt], b[2], b[3]);
                }
            }
        }
        // no trailing barrier: next iteration's barrier provides the fence
    }

    const int qr = lane >> 2;            // 0..7
    const int qc = (lane & 3) * 2;       // 0,2,4,6

    if (!FUSE_LN) {
        // --- epilogue: out = acc + bias + residual (fp32) ---
#pragma unroll
        for (int mt = 0; mt < 4; ++mt) {
#pragma unroll
            for (int nt = 0; nt < 8; ++nt) {
                int gc = 64 * wn + 8 * nt + qc;
                float2 bb = *reinterpret_cast<const float2*>(bias + gc);
                int gr0 = row0 + 64 * wm + 16 * mt + qr;
                int gr1 = gr0 + 8;
                if (gr0 < n) {
                    float2 o = make_float2(d[mt][nt][0] + bb.x, d[mt][nt][1] + bb.y);
                    size_t off = (size_t)gr0 * C + gc;
                    float2 r = *reinterpret_cast<const float2*>(residual + off);
                    o.x += r.x; o.y += r.y;
                    *reinterpret_cast<float2*>(out + off) = o;
                }
                if (gr1 < n) {
                    float2 o = make_float2(d[mt][nt][2] + bb.x, d[mt][nt][3] + bb.y);
                    size_t off = (size_t)gr1 * C + gc;
                    float2 r = *reinterpret_cast<const float2*>(residual + off);
                    o.x += r.x; o.y += r.y;
                    *reinterpret_cast<float2*>(out + off) = o;
                }
            }
        }
    } else {
        // --- fused epilogue: stage acc+bias to smem, LN+FiLM+SiLU -> fp16 ---
        float* accs = reinterpret_cast<float*>(dsm);   // 256 x ACC_PITCH fp32
        __syncthreads();   // all warps done with smem stages & idxsh
#pragma unroll
        for (int mt = 0; mt < 4; ++mt) {
#pragma unroll
            for (int nt = 0; nt < 8; ++nt) {
                int col = 64 * wn + 8 * nt + qc;
                float2 bb = *reinterpret_cast<const float2*>(bias + col);
                int r0 = 64 * wm + 16 * mt + qr;
                float* p0 = accs + r0 * ACC_PITCH + col;
                p0[0] = d[mt][nt][0] + bb.x;
                p0[1] = d[mt][nt][1] + bb.y;
                float* p1 = accs + (r0 + 8) * ACC_PITCH + col;
                p1[0] = d[mt][nt][2] + bb.x;
                p1[1] = d[mt][nt][3] + bb.y;
            }
        }
        __syncthreads();
        // each warp LNs 32 rows; lane holds 4 consecutive floats of the row
#pragma unroll
        for (int rr = 0; rr < 32; ++rr) {
            int r  = wid * 32 + rr;
            int gr = row0 + r;
            if (gr < n) {
                const float* row = accs + r * ACC_PITCH;
                float4 v = *reinterpret_cast<const float4*>(row + lane * 4);
                float s  = v.x + v.y + v.z + v.w;
                float ss = v.x * v.x + v.y * v.y + v.z * v.z + v.w * v.w;
#pragma unroll
                for (int o = 16; o > 0; o >>= 1) {
                    s  += __shfl_xor_sync(0xffffffffu, s, o);
                    ss += __shfl_xor_sync(0xffffffffu, ss, o);
                }
                float mu  = s * (1.0f / 128.0f);
                float inv = rsqrtf(ss * (1.0f / 128.0f) - mu * mu + 1e-6f);
                int b = batch_idx[gr];
                float4 sc = *reinterpret_cast<const float4*>(&g_film[b * 256 + lane * 4]);
                float4 sh = *reinterpret_cast<const float4*>(&g_film[b * 256 + 128 + lane * 4]);
                __half2 h0 = __floats2half2_rn(silu_f((v.x - mu) * inv * sc.x + sh.x),
                                               silu_f((v.y - mu) * inv * sc.y + sh.y));
                __half2 h1 = __floats2half2_rn(silu_f((v.z - mu) * inv * sc.z + sh.z),
                                               silu_f((v.w - mu) * inv * sc.w + sh.w));
                __half2* dst = reinterpret_cast<__half2*>(h3_out + (size_t)gr * C);
                dst[lane * 2]     = h0;
                dst[lane * 2 + 1] = h1;
            }
        }
    }
}

// ---------------------------------------------------------------------------
// Host launcher. conv1 is the 4th launch (the one the profiler captures).
// ---------------------------------------------------------------------------
extern "C" void kernel_launch(void* const* d_in, const int* in_sizes, int n_in,
                              void* d_out, int out_size) {
    const float* feats = (const float*)d_in[0];
    const float* emb   = (const float*)d_in[1];
    const float* g1    = (const float*)d_in[2];
    const float* b1    = (const float*)d_in[3];
    const float* W1    = (const float*)d_in[4];
    const float* cb1   = (const float*)d_in[5];
    const float* W2    = (const float*)d_in[6];
    const float* cb2   = (const float*)d_in[7];
    const float* embW  = (const float*)d_in[8];
    const float* embb  = (const float*)d_in[9];
    const int*   nbr   = (const int*)d_in[10];
    const int*   bidx  = (const int*)d_in[11];
    float*       out   = (float*)d_out;
    (void)n_in; (void)out_size;

    const int n    = in_sizes[0] / C;                  // 200000
    const int nblk = (n + ROWS_CTA - 1) / ROWS_CTA;    // 782

    cudaFuncSetAttribute(conv_mma_kernel<true>,
                         cudaFuncAttributeMaxDynamicSharedMemorySize, DYN_SMEM);
    cudaFuncSetAttribute(conv_mma_kernel<false>,
                         cudaFuncAttributeMaxDynamicSharedMemorySize, DYN_SMEM);

    __half *bufA, *bufH3, *wt1, *wt2;
    cudaGetSymbolAddress((void**)&bufA, g_bufA);
    cudaGetSymbolAddress((void**)&bufH3, g_bufH3);
    cudaGetSymbolAddress((void**)&wt1, g_WT1);
    cudaGetSymbolAddress((void**)&wt2, g_WT2);

    wprep_kernel<<<NC, 256>>>(W1, wt1);                                    // 1
    ln_silu_kernel<<<n / 8, 256>>>(feats, g1, b1);                         // 2
    film_kernel<<<4, 256>>>(emb, embW, embb);                              // 3
    conv_mma_kernel<true><<<nblk, 256, DYN_SMEM>>>(bufA, nbr, wt1, cb1,    // 4 (profiled)
                                                   nullptr, nullptr, bufH3, bidx, n);
    wprep_kernel<<<NC, 256>>>(W2, wt2);                                    // 5
    conv_mma_kernel<false><<<nblk, 256, DYN_SMEM>>>(bufH3, nbr, wt2, cb2,  // 6
                                                    feats, out, nullptr, nullptr, n);
}

// round 13
// speedup vs baseline: 1.1484x; 1.1484x over previous
#include <cuda_runtime.h>
#include <cuda_fp16.h>
#include <cstdint>

// ===========================================================================
// SparseResBlock3D — dense mma.sync fp16 (fp32 accumulate), R10 config
// (CTA 128x128, m32n64 warps, 2 CTA/SM) + invalid-row cp.async skipping:
// invalid gather rows are never staged; their A-fragments are select-zeroed
// in registers after ldmatrix (validity bits precomputed per thread).
//   film = silu(emb) @ emb_W + emb_b
//   h1   = fp16(silu(LN(feats; g,b)))                      -> g_bufA
//   h3   = fp16(silu(LN(conv27(h1,W1)+b1)*(1+s[b])+sh[b])) -> g_bufH3 (fused)
//   out  = conv27(h3, W2) + b2 + feats
// ===========================================================================

#define NROWS     200000
#define C         128
#define TAPS      27
#define ROWS_CTA  128          // CTA output tile rows
#define NC        54           // K-chunks: 27 taps * 2 (K=64 each)
#define NSTAGE    3
#define STAGE_BYTES 32768      // A(16K fp16 128x64) + B(16K fp16 128x64)
#define STAGES_OFF  14336      // idx region: 128*27*4 = 13824B, padded
#define DYN_SMEM  (STAGES_OFF + NSTAGE * STAGE_BYTES)   // 112640 B
#define ACC_PITCH 132          // fp32 epilogue tile pitch (floats)

// ---- scratch (static device globals) ----
__device__ __half g_bufA[(size_t)NROWS * C];    // fp16 h1 (conv1 input)
__device__ __half g_bufH3[(size_t)NROWS * C];   // fp16 h3 (conv2 input)
__device__ float  g_film[4 * 256];              // [b][0:128]=1+scale, [128:256]=shift
__device__ __half g_WT1[(size_t)NC * 8192];     // pre-swizzled fp16 W^T chunks
__device__ __half g_WT2[(size_t)NC * 8192];

// ---------------------------------------------------------------------------
// helpers
// ---------------------------------------------------------------------------
__device__ __forceinline__ float silu_f(float x) { return x / (1.0f + expf(-x)); }

__device__ __forceinline__ uint32_t smem_u32(const void* p) {
    uint32_t a;
    asm("{ .reg .u64 t; cvta.to.shared.u64 t, %1; cvt.u32.u64 %0, t; }" : "=r"(a) : "l"(p));
    return a;
}

__device__ __forceinline__ void cp_async16(uint32_t dst, const void* src) {
    asm volatile("cp.async.cg.shared.global [%0], [%1], 16;"
                 :: "r"(dst), "l"(src));
}
__device__ __forceinline__ void cp_commit() {
    asm volatile("cp.async.commit_group;");
}
template <int N> __device__ __forceinline__ void cp_wait() {
    asm volatile("cp.async.wait_group %0;" :: "n"(N));
}

__device__ __forceinline__ void ldsm4(uint32_t* r, uint32_t addr) {
    asm volatile("ldmatrix.sync.aligned.m8n8.x4.shared.b16 {%0,%1,%2,%3}, [%4];"
                 : "=r"(r[0]), "=r"(r[1]), "=r"(r[2]), "=r"(r[3]) : "r"(addr));
}

__device__ __forceinline__ void mma_f16(float* d, const uint32_t* a,
                                        uint32_t b0, uint32_t b1) {
    asm volatile(
        "mma.sync.aligned.m16n8k16.row.col.f32.f16.f16.f32 "
        "{%0,%1,%2,%3}, {%4,%5,%6,%7}, {%8,%9}, {%0,%1,%2,%3};"
        : "+f"(d[0]), "+f"(d[1]), "+f"(d[2]), "+f"(d[3])
        : "r"(a[0]), "r"(a[1]), "r"(a[2]), "r"(a[3]), "r"(b0), "r"(b1));
}

// ---------------------------------------------------------------------------
// FiLM embedding GEMM.  grid=(4), block=256.
// ---------------------------------------------------------------------------
__global__ void film_kernel(const float* __restrict__ emb,
                            const float* __restrict__ embW,
                            const float* __restrict__ embb) {
    __shared__ float s[512];
    int b = blockIdx.x;
    int c = threadIdx.x;
    for (int e = c; e < 512; e += 256) s[e] = silu_f(emb[b * 512 + e]);
    __syncthreads();
    float acc = embb[c];
#pragma unroll 8
    for (int e = 0; e < 512; ++e) acc = fmaf(s[e], embW[e * 256 + c], acc);
    g_film[b * 256 + c] = (c < 128) ? (1.0f + acc) : acc;
}

// ---------------------------------------------------------------------------
// LN(gamma,beta) + SiLU -> fp16 g_bufA.  One warp per row.
// ---------------------------------------------------------------------------
__global__ void ln_silu_kernel(const float* __restrict__ x,
                               const float* __restrict__ gamma,
                               const float* __restrict__ beta) {
    int row  = blockIdx.x * 8 + (threadIdx.x >> 5);
    int lane = threadIdx.x & 31;
    float4 v = reinterpret_cast<const float4*>(x + (size_t)row * C)[lane];
    float s  = v.x + v.y + v.z + v.w;
    float ss = v.x * v.x + v.y * v.y + v.z * v.z + v.w * v.w;
#pragma unroll
    for (int o = 16; o > 0; o >>= 1) {
        s  += __shfl_xor_sync(0xffffffffu, s, o);
        ss += __shfl_xor_sync(0xffffffffu, ss, o);
    }
    float mu  = s * (1.0f / 128.0f);
    float inv = rsqrtf(ss * (1.0f / 128.0f) - mu * mu + 1e-6f);
    float4 g  = reinterpret_cast<const float4*>(gamma)[lane];
    float4 be = reinterpret_cast<const float4*>(beta)[lane];
    __half2 h0 = __floats2half2_rn(silu_f((v.x - mu) * inv * g.x + be.x),
                                   silu_f((v.y - mu) * inv * g.y + be.y));
    __half2 h1 = __floats2half2_rn(silu_f((v.z - mu) * inv * g.z + be.z),
                                   silu_f((v.w - mu) * inv * g.w + be.w));
    __half2* dst = reinterpret_cast<__half2*>(g_bufA + (size_t)row * C);
    dst[lane * 2]     = h0;
    dst[lane * 2 + 1] = h1;
}

// ---------------------------------------------------------------------------
// Weight prep: transpose to [N,K], fp16-round, XOR-swizzle, pack per chunk.
// ---------------------------------------------------------------------------
__global__ void wprep_kernel(const float* __restrict__ W, __half* __restrict__ WT) {
    int c = blockIdx.x;
    int k = c >> 1, q = c & 1;
    for (int e = threadIdx.x; e < 8192; e += 256) {
        int nn = e >> 6, w = e & 63;
        __half v = __float2half_rn(W[((size_t)k * 128 + q * 64 + w) * 128 + nn]);
        int off = nn * 128 + w * 2;                       // byte offset in tile
        WT[(size_t)c * 8192 + ((off ^ ((off >> 3) & 0x70)) >> 1)] = v;
    }
}

// ---------------------------------------------------------------------------
// Dense mma.sync fp16 sparse conv. 256 threads (8 warps), CTA 128x128.
// Warp tile m32 x n64 (4 m-warps x 2 n-warps). 3-stage cp.async pipeline,
// one barrier per chunk. Invalid rows are NOT staged; their A fragments are
// select-zeroed in registers (validity masks precomputed per thread).
// ---------------------------------------------------------------------------
template <bool FUSE_LN>
__global__ void __launch_bounds__(256, 2)
conv_mma_kernel(const __half* __restrict__ src,
                const int*    __restrict__ nbr,
                const __half* __restrict__ WT,
                const float*  __restrict__ bias,
                const float*  __restrict__ residual,
                float*        __restrict__ out,
                __half*       __restrict__ h3_out,
                const int*    __restrict__ batch_idx,
                int n) {
    extern __shared__ char dsm[];
    int* idxsh = reinterpret_cast<int*>(dsm);

    const int tid  = threadIdx.x;
    const int wid  = tid >> 5;
    const int lane = tid & 31;
    const int row0 = blockIdx.x * ROWS_CTA;
    const uint32_t dsm_u32 = smem_u32(dsm);

    // --- stage neighbor indices (tail rows forced invalid) ---
    for (int l = tid; l < ROWS_CTA * TAPS; l += 256) {
        int gr = row0 + l / TAPS;
        idxsh[l] = (gr < n) ? nbr[(size_t)gr * TAPS + (l % TAPS)] : -1;
    }
    __syncthreads();

    // --- warp tiling ---
    const int wm = wid & 3;          // m-warp (rows 32*wm)
    const int wn = wid >> 2;         // n-warp (cols 64*wn)

    // --- per-thread A-fragment validity masks over all 27 taps ---
    // fragment rows: regs {a0,a2} -> row 32*wm+16*mt+(lane>>2)
    //               regs {a1,a3} -> that row + 8
    uint32_t vmask[4] = {0u, 0u, 0u, 0u};     // [mt*2 + (0: +0 row, 1: +8 row)]
    {
        const int rbase = 32 * wm + (lane >> 2);
        for (int k = 0; k < TAPS; ++k) {
#pragma unroll
            for (int j = 0; j < 4; ++j) {
                int r = rbase + 16 * (j >> 1) + (j & 1) * 8;
                if (idxsh[r * TAPS + k] >= 0) vmask[j] |= (1u << k);
            }
        }
    }

    // loader constants: 2 threads per row, 64B each
    const int a_row  = tid >> 1;
    const int a_half = tid & 1;

    auto load_chunk = [&](int c) {
        int st = c % NSTAGE;
        uint32_t sb = dsm_u32 + STAGES_OFF + st * STAGE_BYTES;
        int k = c >> 1, q = c & 1;
        int idx = idxsh[a_row * TAPS + k];
        if (idx >= 0) {          // invalid rows: skip staging entirely
            const __half* srow = src + (size_t)idx * C + q * 64 + a_half * 32;
#pragma unroll
            for (int i = 0; i < 4; ++i) {
                int off = a_row * 128 + a_half * 64 + i * 16;
                cp_async16(sb + (off ^ ((off >> 3) & 0x70)), srow + i * 8);
            }
        }
        const __half* bsrc = WT + (size_t)c * 8192 + tid * 32;
        uint32_t bd = sb + 16384 + tid * 64;
#pragma unroll
        for (int i = 0; i < 4; ++i) cp_async16(bd + i * 16, bsrc + i * 8);
        cp_commit();
    };

    uint32_t a_rowoff[2];
    int      a_ph[2];
#pragma unroll
    for (int mt = 0; mt < 2; ++mt) {
        int r = 32 * wm + 16 * mt + (lane & 15);
        a_rowoff[mt] = r * 128;
        a_ph[mt]     = r & 7;
    }
    const int a_kbh = lane >> 4;

    uint32_t b_rowoff[4];
    int      b_ph[4];
#pragma unroll
    for (int np = 0; np < 4; ++np) {
        int r = 64 * wn + 16 * np + (lane & 7) + ((lane >> 4) << 3);
        b_rowoff[np] = r * 128;
        b_ph[np]     = r & 7;
    }
    const int b_kbh = (lane >> 3) & 1;

    float d[2][8][4];
#pragma unroll
    for (int mt = 0; mt < 2; ++mt)
#pragma unroll
        for (int nt = 0; nt < 8; ++nt)
#pragma unroll
            for (int j = 0; j < 4; ++j) d[mt][nt][j] = 0.0f;

    // prologue
    load_chunk(0);
    load_chunk(1);

    for (int c = 0; c < NC; ++c) {
        if (c < NC - 1) cp_wait<1>(); else cp_wait<0>();
        __syncthreads();

        if (c + 2 < NC) load_chunk(c + 2);   // issue prefetch BEFORE compute

        const int ktap = c >> 1;
        const uint32_t z0 = ((vmask[0] >> ktap) & 1u) ? 0xFFFFFFFFu : 0u;
        const uint32_t z1 = ((vmask[1] >> ktap) & 1u) ? 0xFFFFFFFFu : 0u;
        const uint32_t z2 = ((vmask[2] >> ktap) & 1u) ? 0xFFFFFFFFu : 0u;
        const uint32_t z3 = ((vmask[3] >> ktap) & 1u) ? 0xFFFFFFFFu : 0u;

        uint32_t sb    = dsm_u32 + STAGES_OFF + (c % NSTAGE) * STAGE_BYTES;
        uint32_t bbase = sb + 16384;

#pragma unroll
        for (int ks = 0; ks < 4; ++ks) {              // 4 x k16 = K64
            uint32_t a0[4], a1[4];
            ldsm4(a0, sb + a_rowoff[0] + ((((ks << 1) | a_kbh) ^ a_ph[0]) << 4));
            ldsm4(a1, sb + a_rowoff[1] + ((((ks << 1) | a_kbh) ^ a_ph[1]) << 4));
            // zero fragments of invalid (unstaged) rows
            a0[0] &= z0; a0[2] &= z0; a0[1] &= z1; a0[3] &= z1;
            a1[0] &= z2; a1[2] &= z2; a1[1] &= z3; a1[3] &= z3;
#pragma unroll
            for (int np = 0; np < 4; ++np) {
                uint32_t b[4];
                ldsm4(b, bbase + b_rowoff[np] + ((((ks << 1) | b_kbh) ^ b_ph[np]) << 4));
                mma_f16(d[0][2 * np],     a0, b[0], b[1]);
                mma_f16(d[0][2 * np + 1], a0, b[2], b[3]);
                mma_f16(d[1][2 * np],     a1, b[0], b[1]);
                mma_f16(d[1][2 * np + 1], a1, b[2], b[3]);
            }
        }
        // no trailing barrier: next iteration's barrier provides the fence
    }

    const int qr = lane >> 2;            // 0..7
    const int qc = (lane & 3) * 2;       // 0,2,4,6

    if (!FUSE_LN) {
        // --- epilogue: out = acc + bias + residual (fp32) ---
#pragma unroll
        for (int mt = 0; mt < 2; ++mt) {
#pragma unroll
            for (int nt = 0; nt < 8; ++nt) {
                int gc = 64 * wn + 8 * nt + qc;
                float2 bb = *reinterpret_cast<const float2*>(bias + gc);
                int gr0 = row0 + 32 * wm + 16 * mt + qr;
                int gr1 = gr0 + 8;
                if (gr0 < n) {
                    float2 o = make_float2(d[mt][nt][0] + bb.x, d[mt][nt][1] + bb.y);
                    size_t off = (size_t)gr0 * C + gc;
                    float2 r = *reinterpret_cast<const float2*>(residual + off);
                    o.x += r.x; o.y += r.y;
                    *reinterpret_cast<float2*>(out + off) = o;
                }
                if (gr1 < n) {
                    float2 o = make_float2(d[mt][nt][2] + bb.x, d[mt][nt][3] + bb.y);
                    size_t off = (size_t)gr1 * C + gc;
                    float2 r = *reinterpret_cast<const float2*>(residual + off);
                    o.x += r.x; o.y += r.y;
                    *reinterpret_cast<float2*>(out + off) = o;
                }
            }
        }
    } else {
        // --- fused epilogue: stage acc+bias to smem, LN+FiLM+SiLU -> fp16 ---
        float* accs = reinterpret_cast<float*>(dsm);   // 128 x ACC_PITCH fp32
        __syncthreads();   // all warps done with smem stages & idxsh
#pragma unroll
        for (int mt = 0; mt < 2; ++mt) {
#pragma unroll
            for (int nt = 0; nt < 8; ++nt) {
                int col = 64 * wn + 8 * nt + qc;
                float2 bb = *reinterpret_cast<const float2*>(bias + col);
                int r0 = 32 * wm + 16 * mt + qr;
                float* p0 = accs + r0 * ACC_PITCH + col;
                p0[0] = d[mt][nt][0] + bb.x;
                p0[1] = d[mt][nt][1] + bb.y;
                float* p1 = accs + (r0 + 8) * ACC_PITCH + col;
                p1[0] = d[mt][nt][2] + bb.x;
                p1[1] = d[mt][nt][3] + bb.y;
            }
        }
        __syncthreads();
        // each warp LNs 16 rows; lane holds 4 consecutive floats of the row
#pragma unroll
        for (int rr = 0; rr < 16; ++rr) {
            int r  = wid * 16 + rr;
            int gr = row0 + r;
            if (gr < n) {
                const float* row = accs + r * ACC_PITCH;
                float4 v = *reinterpret_cast<const float4*>(row + lane * 4);
                float s  = v.x + v.y + v.z + v.w;
                float ss = v.x * v.x + v.y * v.y + v.z * v.z + v.w * v.w;
#pragma unroll
                for (int o = 16; o > 0; o >>= 1) {
                    s  += __shfl_xor_sync(0xffffffffu, s, o);
                    ss += __shfl_xor_sync(0xffffffffu, ss, o);
                }
                float mu  = s * (1.0f / 128.0f);
                float inv = rsqrtf(ss * (1.0f / 128.0f) - mu * mu + 1e-6f);
                int b = batch_idx[gr];
                float4 sc = *reinterpret_cast<const float4*>(&g_film[b * 256 + lane * 4]);
                float4 sh = *reinterpret_cast<const float4*>(&g_film[b * 256 + 128 + lane * 4]);
                __half2 h0 = __floats2half2_rn(silu_f((v.x - mu) * inv * sc.x + sh.x),
                                               silu_f((v.y - mu) * inv * sc.y + sh.y));
                __half2 h1 = __floats2half2_rn(silu_f((v.z - mu) * inv * sc.z + sh.z),
                                               silu_f((v.w - mu) * inv * sc.w + sh.w));
                __half2* dst = reinterpret_cast<__half2*>(h3_out + (size_t)gr * C);
                dst[lane * 2]     = h0;
                dst[lane * 2 + 1] = h1;
            }
        }
    }
}

// ---------------------------------------------------------------------------
// Host launcher. conv1 is the 4th launch (the one the profiler captures).
// ---------------------------------------------------------------------------
extern "C" void kernel_launch(void* const* d_in, const int* in_sizes, int n_in,
                              void* d_out, int out_size) {
    const float* feats = (const float*)d_in[0];
    const float* emb   = (const float*)d_in[1];
    const float* g1    = (const float*)d_in[2];
    const float* b1    = (const float*)d_in[3];
    const float* W1    = (const float*)d_in[4];
    const float* cb1   = (const float*)d_in[5];
    const float* W2    = (const float*)d_in[6];
    const float* cb2   = (const float*)d_in[7];
    const float* embW  = (const float*)d_in[8];
    const float* embb  = (const float*)d_in[9];
    const int*   nbr   = (const int*)d_in[10];
    const int*   bidx  = (const int*)d_in[11];
    float*       out   = (float*)d_out;
    (void)n_in; (void)out_size;

    const int n    = in_sizes[0] / C;                  // 200000
    const int nblk = (n + ROWS_CTA - 1) / ROWS_CTA;    // 1563

    cudaFuncSetAttribute(conv_mma_kernel<true>,
                         cudaFuncAttributeMaxDynamicSharedMemorySize, DYN_SMEM);
    cudaFuncSetAttribute(conv_mma_kernel<false>,
                         cudaFuncAttributeMaxDynamicSharedMemorySize, DYN_SMEM);

    __half *bufA, *bufH3, *wt1, *wt2;
    cudaGetSymbolAddress((void**)&bufA, g_bufA);
    cudaGetSymbolAddress((void**)&bufH3, g_bufH3);
    cudaGetSymbolAddress((void**)&wt1, g_WT1);
    cudaGetSymbolAddress((void**)&wt2, g_WT2);

    wprep_kernel<<<NC, 256>>>(W1, wt1);                                    // 1
    ln_silu_kernel<<<n / 8, 256>>>(feats, g1, b1);                         // 2
    film_kernel<<<4, 256>>>(emb, embW, embb);                              // 3
    conv_mma_kernel<true><<<nblk, 256, DYN_SMEM>>>(bufA, nbr, wt1, cb1,    // 4 (profiled)
                                                   nullptr, nullptr, bufH3, bidx, n);
    wprep_kernel<<<NC, 256>>>(W2, wt2);                                    // 5
    conv_mma_kernel<false><<<nblk, 256, DYN_SMEM>>>(bufH3, nbr, wt2, cb2,  // 6
                                                    feats, out, nullptr, nullptr, n);
}